// round 8
// baseline (speedup 1.0000x reference)
#include <cuda_runtime.h>
#include <cuda_bf16.h>
#include <cstddef>
#include <cstdint>

// ---------------- problem constants ----------------
#define U_  1024
#define B_  8
#define D_  512
#define H_  8
#define HD_ 64
#define CL_ 64
#define RC_ 4
#define C_  16
#define R_  64
#define S_  16
#define M_  15
#define Q_  1104
#define KV_ 1103
#define NEG_INF_ (-100000000.0f)
#define SCALING_ 0.125f

// ---------------- helpers ----------------
__device__ __forceinline__ uint32_t smem_u32(const void* p) {
    uint32_t a;
    asm("{ .reg .u64 t; cvta.to.shared.u64 t, %1; cvt.u32.u64 %0, t; }" : "=r"(a) : "l"(p));
    return a;
}
#define SWZ128(o) ((o) ^ (((o) >> 3) & 0x70))

__device__ __forceinline__ void ldmx4(uint32_t* r, uint32_t addr) {
    asm volatile("ldmatrix.sync.aligned.m8n8.x4.shared.b16 {%0,%1,%2,%3}, [%4];"
                 : "=r"(r[0]), "=r"(r[1]), "=r"(r[2]), "=r"(r[3]) : "r"(addr));
}
__device__ __forceinline__ void ldmx4t(uint32_t* r, uint32_t addr) {
    asm volatile("ldmatrix.sync.aligned.m8n8.x4.trans.shared.b16 {%0,%1,%2,%3}, [%4];"
                 : "=r"(r[0]), "=r"(r[1]), "=r"(r[2]), "=r"(r[3]) : "r"(addr));
}
__device__ __forceinline__ void mma16816(float* d, const uint32_t* a,
                                         uint32_t b0, uint32_t b1) {
    asm volatile(
        "mma.sync.aligned.m16n8k16.row.col.f32.bf16.bf16.f32 "
        "{%0,%1,%2,%3}, {%4,%5,%6,%7}, {%8,%9}, {%0,%1,%2,%3};"
        : "+f"(d[0]), "+f"(d[1]), "+f"(d[2]), "+f"(d[3])
        : "r"(a[0]), "r"(a[1]), "r"(a[2]), "r"(a[3]), "r"(b0), "r"(b1));
}
__device__ __forceinline__ void cpa16(uint32_t dst, const void* src) {
    asm volatile("cp.async.cg.shared.global [%0], [%1], 16;" :: "r"(dst), "l"(src));
}
#define CPA_COMMIT() asm volatile("cp.async.commit_group;" ::: "memory")
#define CPA_WAIT1()  asm volatile("cp.async.wait_group 1;" ::: "memory")
#define CPA_WAIT0()  asm volatile("cp.async.wait_group 0;" ::: "memory")

// ---------------- scratch (device globals; no allocs) ----------------
__device__ float g_q[(size_t)Q_ * B_ * D_];
__device__ float g_kv[(size_t)KV_ * B_ * 2 * D_];
__device__ float g_pos[(size_t)192 * D_];
__device__ float g_attn[(size_t)Q_ * B_ * D_];
__device__ float g_bd[(size_t)64 * 1024 * 128];
__device__ __nv_bfloat16 g_whi[1024 * 512];
__device__ __nv_bfloat16 g_wlo[1024 * 512];
__device__ __nv_bfloat16 g_ahi[(size_t)9216 * 512];
__device__ __nv_bfloat16 g_alo[(size_t)9216 * 512];
__device__ __nv_bfloat16 g_qhi[(size_t)Q_ * B_ * D_];
__device__ __nv_bfloat16 g_qlo[(size_t)Q_ * B_ * D_];
__device__ __nv_bfloat16 g_kvhi[(size_t)KV_ * B_ * 2 * D_];
__device__ __nv_bfloat16 g_kvlo[(size_t)KV_ * B_ * 2 * D_];

// =====================================================================
// Weight split
// =====================================================================
__global__ void conv_w_kernel(const float* __restrict__ src, int n)
{
    int i = blockIdx.x * 256 + threadIdx.x;
    if (i < n) {
        float a = src[i];
        __nv_bfloat16 h = __float2bfloat16(a);
        g_whi[i] = h;
        g_wlo[i] = __float2bfloat16(a - __bfloat162float(h));
    }
}

// =====================================================================
// A split (concat of <=4 row segments)
// =====================================================================
__global__ void conv_a_kernel(const float* __restrict__ A0, const float* __restrict__ A1,
                              const float* __restrict__ A2, const float* __restrict__ A3,
                              int r1, int r2, int r3, int nrows, int dst_row0)
{
    int i = blockIdx.x * 256 + threadIdx.x;
    if (i >= nrows * 128) return;
    int row = i >> 7, c4 = (i & 127) * 4;
    const float* src; int lr;
    if (row < r1)      { src = A0; lr = row; }
    else if (row < r2) { src = A1; lr = row - r1; }
    else if (row < r3) { src = A2; lr = row - r2; }
    else               { src = A3; lr = row - r3; }
    float4 v = *(const float4*)(src + (size_t)lr * 512 + c4);
    float vv[4] = {v.x, v.y, v.z, v.w};
    ushort hi[4], lo[4];
    #pragma unroll
    for (int j = 0; j < 4; j++) {
        __nv_bfloat16 h = __float2bfloat16(vv[j]);
        __nv_bfloat16 l = __float2bfloat16(vv[j] - __bfloat162float(h));
        hi[j] = __bfloat16_as_ushort(h);
        lo[j] = __bfloat16_as_ushort(l);
    }
    size_t o = (size_t)(dst_row0 + row) * 512 + c4;
    *(uint2*)&g_ahi[o] = make_uint2((uint32_t)hi[0] | ((uint32_t)hi[1] << 16),
                                    (uint32_t)hi[2] | ((uint32_t)hi[3] << 16));
    *(uint2*)&g_alo[o] = make_uint2((uint32_t)lo[0] | ((uint32_t)lo[1] << 16),
                                    (uint32_t)lo[2] | ((uint32_t)lo[3] << 16));
}

// =====================================================================
// HMMA GEMM with cp.async 3-stage pipeline; optional bf16 hi/lo dual-out
// =====================================================================
#define GSM_TOTAL 98304

__global__ __launch_bounds__(256, 2) void gemm_tc_kernel(
    const __nv_bfloat16* __restrict__ Ahi, const __nv_bfloat16* __restrict__ Alo,
    float* __restrict__ Cm, __nv_bfloat16* __restrict__ Chi,
    __nv_bfloat16* __restrict__ Clo,
    int Mr, int ldc, const float* __restrict__ bias)
{
    extern __shared__ char gsm[];
    const uint32_t sb = smem_u32(gsm);
    const int tid = threadIdx.x;
    const int wid = tid >> 5, lane = tid & 31;
    const int wm = wid & 3, wn = wid >> 2;
    const int row0 = blockIdx.y * 128, col0 = blockIdx.x * 128;
    const int car = tid >> 3, cg8 = tid & 7;

    auto issue = [&](int c) {
        const int seg = c >> 3;
        const int k0 = (c & 7) * 64;
        const __nv_bfloat16* asrc = (seg == 1) ? Alo : Ahi;
        const __nv_bfloat16* wsrc = (seg == 2) ? g_wlo : g_whi;
        char* abuf = gsm + (c % 3) * 16384;
        char* bbuf = gsm + 49152 + (c % 3) * 16384;
        #pragma unroll
        for (int t = 0; t < 4; t++) {
            int ar = car + t * 32;
            int gr = row0 + ar; if (gr >= Mr) gr = Mr - 1;
            cpa16(smem_u32(abuf) + SWZ128((uint32_t)(ar * 128 + cg8 * 16)),
                  asrc + (size_t)gr * 512 + k0 + cg8 * 8);
        }
        #pragma unroll
        for (int t = 0; t < 4; t++) {
            int br = car + t * 32;
            cpa16(smem_u32(bbuf) + SWZ128((uint32_t)(br * 128 + cg8 * 16)),
                  wsrc + (size_t)(col0 + br) * 512 + k0 + cg8 * 8);
        }
        CPA_COMMIT();
    };

    float acc[2][8][4] = {};
    issue(0);
    issue(1);

    const int l15 = lane & 15, lh = lane >> 4;
    const int l8 = lane & 7, lg = lane >> 3;

    for (int c = 0; c < 24; c++) {
        if (c < 23) CPA_WAIT1(); else CPA_WAIT0();
        __syncthreads();
        const uint32_t Ab = sb + (c % 3) * 16384;
        const uint32_t Bb = sb + 49152 + (c % 3) * 16384;
        #pragma unroll
        for (int s = 0; s < 4; s++) {
            uint32_t afr[2][4];
            #pragma unroll
            for (int mt = 0; mt < 2; mt++) {
                int r = wm * 32 + mt * 16 + l15;
                uint32_t o = (uint32_t)(r * 128 + s * 32 + lh * 16);
                ldmx4(afr[mt], Ab + SWZ128(o));
            }
            uint32_t bfr[4][4];
            #pragma unroll
            for (int bt = 0; bt < 4; bt++) {
                int n = wn * 64 + bt * 16 + ((lg >> 1) ? 8 : 0) + l8;
                uint32_t o = (uint32_t)(n * 128 + s * 32 + (lg & 1) * 16);
                ldmx4(bfr[bt], Bb + SWZ128(o));
            }
            #pragma unroll
            for (int mt = 0; mt < 2; mt++)
                #pragma unroll
                for (int nt = 0; nt < 8; nt++) {
                    int bt = nt >> 1, sub = nt & 1;
                    mma16816(acc[mt][nt], afr[mt], bfr[bt][2*sub], bfr[bt][2*sub+1]);
                }
        }
        if (c + 2 < 24) issue(c + 2);
    }

    const int quad = lane >> 2, tq = lane & 3;
    #pragma unroll
    for (int mt = 0; mt < 2; mt++) {
        #pragma unroll
        for (int nt = 0; nt < 8; nt++) {
            int gr0 = row0 + wm * 32 + mt * 16 + quad;
            int gc  = col0 + wn * 64 + nt * 8 + tq * 2;
            float b0 = bias ? bias[gc]     : 0.f;
            float b1 = bias ? bias[gc + 1] : 0.f;
            #pragma unroll
            for (int half = 0; half < 2; half++) {
                int gr = gr0 + half * 8;
                if (gr < Mr) {
                    float2 v = {acc[mt][nt][half*2+0] + b0, acc[mt][nt][half*2+1] + b1};
                    *(float2*)&Cm[(size_t)gr * ldc + gc] = v;
                    if (Chi) {
                        __nv_bfloat16 h0 = __float2bfloat16(v.x);
                        __nv_bfloat16 h1 = __float2bfloat16(v.y);
                        __nv_bfloat16 l0 = __float2bfloat16(v.x - __bfloat162float(h0));
                        __nv_bfloat16 l1 = __float2bfloat16(v.y - __bfloat162float(h1));
                        *(uint32_t*)&Chi[(size_t)gr * ldc + gc] =
                            (uint32_t)__bfloat16_as_ushort(h0) | ((uint32_t)__bfloat16_as_ushort(h1) << 16);
                        *(uint32_t*)&Clo[(size_t)gr * ldc + gc] =
                            (uint32_t)__bfloat16_as_ushort(l0) | ((uint32_t)__bfloat16_as_ushort(l1) << 16);
                    }
                }
            }
        }
    }
}

// =====================================================================
// BD kernel (unchanged): banded qv.pos -> g_bd[bh][1024][128]
// =====================================================================
#define BDSM_FLOATS (64*65 + 64*193 + 192 + 64)

__global__ __launch_bounds__(256) void bd_kernel(const float* __restrict__ pbv)
{
    extern __shared__ float smf[];
    float* qv      = smf;
    float* Pt      = smf + 64 * 65;
    float* bias_vp = Pt + 64 * 193;
    float* pbv_s   = bias_vp + 192;

    const int c = blockIdx.x, bh = blockIdx.y;
    const int b = bh >> 3, h = bh & 7;
    const int tid = threadIdx.x;
    const int pbase = (c == 0) ? 127 : 63;

    for (int idx = tid; idx < 64 * 64; idx += 256) {
        int u = idx >> 6, k = idx & 63;
        qv[u * 65 + k] = g_q[((size_t)(R_ + c * 64 + u) * B_ + b) * D_ + h * 64 + k];
    }
    for (int idx = tid; idx < 191 * 64; idx += 256) {
        int pl = idx >> 6, k = idx & 63;
        Pt[k * 193 + pl] = g_pos[(size_t)pl * D_ + h * 64 + k];
    }
    if (tid < 64) pbv_s[tid] = pbv[h * 64 + tid];
    __syncthreads();

    if (tid < 191) {
        float s = 0.f;
        #pragma unroll 8
        for (int k = 0; k < 64; k++) s += pbv_s[k] * Pt[k * 193 + tid];
        bias_vp[tid] = s;
    }
    __syncthreads();

    const int ty = tid >> 4, tx = tid & 15;
    const int plb = pbase - ty + tx;
    float accb[4][8] = {};
    for (int kk = 0; kk < 64; kk++) {
        float qq[4];
        #pragma unroll
        for (int a = 0; a < 4; a++) qq[a] = qv[(ty + 16 * a) * 65 + kk];
        float pv[11];
        #pragma unroll
        for (int t = 0; t < 11; t++) {
            int pl = plb + 16 * (t - 3);
            pl = (pl < 0) ? 0 : (pl > 190 ? 190 : pl);
            pv[t] = Pt[kk * 193 + pl];
        }
        #pragma unroll
        for (int a = 0; a < 4; a++)
            #pragma unroll
            for (int bb = 0; bb < 8; bb++)
                accb[a][bb] += qq[a] * pv[bb - a + 3];
    }
    float* dst = g_bd + ((size_t)bh * 1024 + c * 64) * 128;
    #pragma unroll
    for (int a = 0; a < 4; a++) {
        int u = ty + 16 * a;
        #pragma unroll
        for (int bb = 0; bb < 8; bb++) {
            int j = tx + 16 * bb;
            int pl = pbase - u + j;
            pl = (pl < 0) ? 0 : (pl > 190 ? 190 : pl);
            dst[(size_t)u * 128 + j] = accb[a][bb] + bias_vp[pl];
        }
    }
}

// =====================================================================
// Fused attention v3: HMMA AC + softmax + HMMA PV. 256 threads.
// smem layout (bytes):
//   QHI 0      (96x128)      QLO 12288
//   KHI 24576  (192x128)     KLO 49152     (reused for Vhi/Vlo)
//   SS  73728  fp32 80 x stride196 (62720)
//   PHI 136448 bf16 96 x stride400B
//   PLO 174848
//   BU  213248 (192 f)  PBU 214016 (64 f)
// =====================================================================
#define FA_QHI 0
#define FA_QLO 12288
#define FA_KHI 24576
#define FA_KLO 49152
#define FA_SS  73728
#define FA_PHI 136448
#define FA_PLO 174848
#define FA_BU  213248
#define FA_PBU 214016
#define FA_TOTAL 214272

__global__ __launch_bounds__(256) void fused_attn_kernel(
    const int* __restrict__ lengths,
    const float* __restrict__ pbu)
{
    extern __shared__ char fsm[];
    const uint32_t sb = smem_u32(fsm);
    float* bias_u = (float*)(fsm + FA_BU);
    float* pbu_s  = (float*)(fsm + FA_PBU);

    const int c = blockIdx.x, bh = blockIdx.y;
    const int b = bh >> 3, h = bh & 7;
    const int tid = threadIdx.x;
    const int wid = tid >> 5, lane = tid & 31;
    const int ustart = (c == 0) ? 0 : (c - 1) * CL_;
    const int n_utt = (c == 0) ? 64 : 128;
    const int ncols = c + 4 + n_utt;
    const int len_b = lengths[b];

    // ---- zero P buffers (both, fully) ----
    {
        uint4 z = make_uint4(0, 0, 0, 0);
        for (int i = tid * 16; i < 2 * 38400; i += 256 * 16)
            *(uint4*)(fsm + FA_PHI + i) = z;
        // zero K rows >= ncols (becomes V pad too)
        for (int i = tid * 16; i < (192 - ncols) * 128; i += 256 * 16) {
            *(uint4*)(fsm + FA_KHI + ncols * 128 + i) = z;
            *(uint4*)(fsm + FA_KLO + ncols * 128 + i) = z;
        }
    }

    // ---- cp.async loads: Q (69 rows), K (ncols rows) hi+lo ----
    for (int idx = tid; idx < 69 * 8; idx += 256) {
        int r = idx >> 3, ch = idx & 7;
        int qrow = (r < 4) ? c * 4 + r
                 : (r < 68 ? R_ + c * 64 + (r - 4) : R_ + U_ + c);
        size_t go = ((size_t)qrow * B_ + b) * 512 + h * 64 + ch * 8;
        uint32_t so = SWZ128((uint32_t)(r * 128 + ch * 16));
        cpa16(sb + FA_QHI + so, g_qhi + go);
        cpa16(sb + FA_QLO + so, g_qlo + go);
    }
    for (int idx = tid; idx < ncols * 8; idx += 256) {
        int i = idx >> 3, ch = idx & 7;
        int kvrow = (i < c) ? i
                  : (i < c + 4 ? M_ + c * 4 + (i - c)
                               : M_ + R_ + ustart + (i - c - 4));
        size_t go = ((size_t)kvrow * B_ + b) * 1024 + h * 64 + ch * 8;
        uint32_t so = SWZ128((uint32_t)(i * 128 + ch * 16));
        cpa16(sb + FA_KHI + so, g_kvhi + go);
        cpa16(sb + FA_KLO + so, g_kvlo + go);
    }
    CPA_COMMIT();
    if (tid < 64) pbu_s[tid] = pbu[h * 64 + tid];
    CPA_WAIT0();
    __syncthreads();

    const int wm = wid >> 2, wn = wid & 3;      // 2 x 4 warps
    const int l15 = lane & 15, lh = lane >> 4;
    const int l8 = lane & 7, lg = lane >> 3;
    const int quad = lane >> 2, tq = lane & 3;

    // ---- AC: scores = Q.K^T via HMMA, 3 split-precision passes ----
    {
        float acc[3][6][4] = {};
        #pragma unroll
        for (int pass = 0; pass < 3; pass++) {
            const uint32_t Ab = sb + ((pass == 1) ? FA_QLO : FA_QHI);
            const uint32_t Bb = sb + ((pass == 2) ? FA_KLO : FA_KHI);
            #pragma unroll
            for (int s = 0; s < 4; s++) {
                uint32_t afr[3][4];
                #pragma unroll
                for (int mt = 0; mt < 3; mt++) {
                    int r = wm * 48 + mt * 16 + l15;
                    ldmx4(afr[mt], Ab + SWZ128((uint32_t)(r * 128 + s * 32 + lh * 16)));
                }
                uint32_t bfr[3][4];
                #pragma unroll
                for (int nt = 0; nt < 3; nt++) {
                    int n = wn * 48 + nt * 16 + ((lg >> 1) ? 8 : 0) + l8;
                    ldmx4(bfr[nt], Bb + SWZ128((uint32_t)(n * 128 + s * 32 + (lg & 1) * 16)));
                }
                #pragma unroll
                for (int mt = 0; mt < 3; mt++)
                    #pragma unroll
                    for (int nt = 0; nt < 3; nt++) {
                        mma16816(acc[mt][nt*2+0], afr[mt], bfr[nt][0], bfr[nt][1]);
                        mma16816(acc[mt][nt*2+1], afr[mt], bfr[nt][2], bfr[nt][3]);
                    }
            }
        }
        // store scores (fp32, stride 196)
        #pragma unroll
        for (int mt = 0; mt < 3; mt++) {
            int r0 = wm * 48 + mt * 16 + quad;
            #pragma unroll
            for (int n8 = 0; n8 < 6; n8++) {
                int col = wn * 48 + (n8 >> 1) * 16 + (n8 & 1) * 8 + tq * 2;
                if (r0 < 80) {
                    float2 v = {acc[mt][n8][0], acc[mt][n8][1]};
                    *(float2*)(fsm + FA_SS + (size_t)(r0 * 196 + col) * 4) = v;
                }
                if (r0 + 8 < 80) {
                    float2 v = {acc[mt][n8][2], acc[mt][n8][3]};
                    *(float2*)(fsm + FA_SS + (size_t)((r0 + 8) * 196 + col) * 4) = v;
                }
            }
        }
    }

    // ---- bias_u[i] = pbu . K_i (exact fp32 from gmem) ----
    if (tid < 192) {
        float s = 0.f;
        if (tid < ncols) {
            int i = tid;
            int kvrow = (i < c) ? i
                      : (i < c + 4 ? M_ + c * 4 + (i - c)
                                   : M_ + R_ + ustart + (i - c - 4));
            const float4* kp = (const float4*)(g_kv + ((size_t)kvrow * B_ + b) * 1024 + h * 64);
            #pragma unroll 4
            for (int k4 = 0; k4 < 16; k4++) {
                float4 kvv = kp[k4];
                s += pbu_s[k4*4+0] * kvv.x + pbu_s[k4*4+1] * kvv.y
                   + pbu_s[k4*4+2] * kvv.z + pbu_s[k4*4+3] * kvv.w;
            }
        }
        bias_u[tid] = s;
    }
    __syncthreads();

    // ---- V load (cp.async, into K region) ----
    for (int idx = tid; idx < ncols * 8; idx += 256) {
        int i = idx >> 3, ch = idx & 7;
        int kvrow = (i < c) ? i
                  : (i < c + 4 ? M_ + c * 4 + (i - c)
                               : M_ + R_ + ustart + (i - c - 4));
        size_t go = ((size_t)kvrow * B_ + b) * 1024 + 512 + h * 64 + ch * 8;
        uint32_t so = SWZ128((uint32_t)(i * 128 + ch * 16));
        cpa16(sb + FA_KHI + so, g_kvhi + go);
        cpa16(sb + FA_KLO + so, g_kvlo + go);
    }
    CPA_COMMIT();

    // ---- softmax: scale + bias_u + BD + masks; emit P hi/lo bf16 ----
    {
        const int limit_j = len_b - ustart;
        const int uc0 = c + 4;
        for (int r = wid; r < 69; r += 8) {
            const bool is_utt = (r >= 4) && (r < 68);
            const float* bdrow = g_bd + ((size_t)bh * 1024 + c * 64 + (r - 4)) * 128;
            float vals[6];
            float mx = -3.4e38f;
            #pragma unroll
            for (int g = 0; g < 6; g++) {
                int i = lane + 32 * g;
                float v = -3.4e38f;
                if (i < ncols) {
                    float s = *(const float*)(fsm + FA_SS + (size_t)(r * 196 + i) * 4) + bias_u[i];
                    if (i >= uc0) {
                        int j = i - uc0;
                        if (is_utt) s += bdrow[j];
                        v = (j >= limit_j) ? NEG_INF_ : s * SCALING_;
                    } else {
                        v = s * SCALING_;
                    }
                }
                vals[g] = v;
                mx = fmaxf(mx, v);
            }
            #pragma unroll
            for (int o = 16; o > 0; o >>= 1) mx = fmaxf(mx, __shfl_xor_sync(~0u, mx, o));
            float sum = 0.f;
            #pragma unroll
            for (int g = 0; g < 6; g++) {
                float e = __expf(vals[g] - mx);
                vals[g] = e;
                sum += e;
            }
            #pragma unroll
            for (int o = 16; o > 0; o >>= 1) sum += __shfl_xor_sync(~0u, sum, o);
            float inv = 1.f / sum;
            #pragma unroll
            for (int g = 0; g < 6; g++) {
                int i = lane + 32 * g;
                float p = vals[g] * inv;
                __nv_bfloat16 hp = __float2bfloat16(p);
                __nv_bfloat16 lp = __float2bfloat16(p - __bfloat162float(hp));
                *(ushort*)(fsm + FA_PHI + r * 400 + i * 2) = __bfloat16_as_ushort(hp);
                *(ushort*)(fsm + FA_PLO + r * 400 + i * 2) = __bfloat16_as_ushort(lp);
            }
        }
    }
    CPA_WAIT0();
    __syncthreads();

    // ---- PV: out = P.V via HMMA (ldmatrix.trans for V), 3 passes ----
    {
        float accp[3][2][4] = {};
        #pragma unroll
        for (int pass = 0; pass < 3; pass++) {
            const uint32_t Ab = sb + ((pass == 1) ? FA_PLO : FA_PHI);
            const uint32_t Bb = sb + ((pass == 2) ? FA_KLO : FA_KHI);
            #pragma unroll
            for (int kk = 0; kk < 12; kk++) {
                uint32_t afr[3][4];
                #pragma unroll
                for (int mt = 0; mt < 3; mt++) {
                    int r = wm * 48 + mt * 16 + l15;
                    ldmx4(afr[mt], Ab + (uint32_t)(r * 400 + kk * 32 + lh * 16));
                }
                uint32_t bfr[4];
                ldmx4t(bfr, Bb + SWZ128((uint32_t)((kk * 16 + l15) * 128 + wn * 32 + lh * 16)));
                #pragma unroll
                for (int mt = 0; mt < 3; mt++) {
                    mma16816(accp[mt][0], afr[mt], bfr[0], bfr[1]);
                    mma16816(accp[mt][1], afr[mt], bfr[2], bfr[3]);
                }
            }
        }
        #pragma unroll
        for (int mt = 0; mt < 3; mt++) {
            int r0 = wm * 48 + mt * 16 + quad;
            #pragma unroll
            for (int half = 0; half < 2; half++) {
                int r = r0 + half * 8;
                if (r < 69) {
                    int qrow = (r < 4) ? c * 4 + r
                             : (r < 68 ? R_ + c * 64 + (r - 4) : R_ + U_ + c);
                    float* dst = g_attn + ((size_t)qrow * B_ + b) * 512 + h * 64;
                    #pragma unroll
                    for (int n = 0; n < 2; n++) {
                        int d = wn * 16 + n * 8 + tq * 2;
                        float2 v = {accp[mt][n][half*2+0], accp[mt][n][half*2+1]};
                        *(float2*)(dst + d) = v;
                    }
                }
            }
        }
    }
}

// ---------------- out_mem = clip(attn[R+U:], -10, 10) ----------------
__global__ void clip_kernel(float* __restrict__ out)
{
    const size_t off = (size_t)(R_ + U_) * B_ * D_;
    int i = blockIdx.x * 256 + threadIdx.x;
    float v = g_attn[off + i];
    out[off + i] = fminf(10.f, fmaxf(-10.f, v));
}

// ---------------- launch ----------------
extern "C" void kernel_launch(void* const* d_in, const int* in_sizes, int n_in,
                              void* d_out, int out_size)
{
    const float* utt    = (const float*)d_in[0];
    const int*   lens   = (const int*)  d_in[1];
    const float* rc     = (const float*)d_in[2];
    const float* summ   = (const float*)d_in[3];
    const float* mem    = (const float*)d_in[4];
    const float* pos_e  = (const float*)d_in[6];
    const float* W_kv   = (const float*)d_in[7];
    const float* b_kv   = (const float*)d_in[8];
    const float* W_q    = (const float*)d_in[9];
    const float* b_q    = (const float*)d_in[10];
    const float* W_out  = (const float*)d_in[11];
    const float* b_out  = (const float*)d_in[12];
    const float* W_pos  = (const float*)d_in[13];
    const float* pbu    = (const float*)d_in[14];
    const float* pbv    = (const float*)d_in[15];
    float* out = (float*)d_out;

    float *q_buf, *kv_buf, *pos_buf, *attn_buf;
    __nv_bfloat16 *ahi, *alo, *qhi, *qlo, *kvhi, *kvlo;
    cudaGetSymbolAddress((void**)&q_buf,    g_q);
    cudaGetSymbolAddress((void**)&kv_buf,   g_kv);
    cudaGetSymbolAddress((void**)&pos_buf,  g_pos);
    cudaGetSymbolAddress((void**)&attn_buf, g_attn);
    cudaGetSymbolAddress((void**)&ahi,      g_ahi);
    cudaGetSymbolAddress((void**)&alo,      g_alo);
    cudaGetSymbolAddress((void**)&qhi,      g_qhi);
    cudaGetSymbolAddress((void**)&qlo,      g_qlo);
    cudaGetSymbolAddress((void**)&kvhi,     g_kvhi);
    cudaGetSymbolAddress((void**)&kvlo,     g_kvlo);

    const size_t SMEM_BD = (size_t)BDSM_FLOATS * 4;
    cudaFuncSetAttribute(fused_attn_kernel,
                         cudaFuncAttributeMaxDynamicSharedMemorySize, FA_TOTAL);
    cudaFuncSetAttribute(bd_kernel,
                         cudaFuncAttributeMaxDynamicSharedMemorySize, (int)SMEM_BD);
    cudaFuncSetAttribute(gemm_tc_kernel,
                         cudaFuncAttributeMaxDynamicSharedMemorySize, GSM_TOTAL);

    const dim3 blk(256);
    const float* pos_src = pos_e + (size_t)(U_ - 128) * D_;

    // ---- A conversion: concat [mem|rc|utt|summ] + pos rows ----
    conv_a_kernel<<<dim3((8952 * 128 + 255) / 256), blk>>>(
        mem, rc, utt, summ, 120, 632, 8824, 8952, 0);
    conv_a_kernel<<<dim3((191 * 128 + 255) / 256), blk>>>(
        pos_src, pos_src, pos_src, pos_src, 191, 191, 191, 191, 8952);

    // ---- projections (q/kv with bf16 dual-output) ----
    conv_w_kernel<<<dim3(1024), blk>>>(W_q, 512 * 512);
    gemm_tc_kernel<<<dim3(4, 69), blk, GSM_TOTAL>>>(
        ahi + (size_t)120 * 512, alo + (size_t)120 * 512,
        q_buf, qhi, qlo, Q_ * B_, D_, b_q);

    conv_w_kernel<<<dim3(2048), blk>>>(W_kv, 1024 * 512);
    gemm_tc_kernel<<<dim3(8, 69), blk, GSM_TOTAL>>>(
        ahi, alo, kv_buf, kvhi, kvlo, KV_ * B_, 2 * D_, b_kv);

    conv_w_kernel<<<dim3(1024), blk>>>(W_pos, 512 * 512);
    gemm_tc_kernel<<<dim3(4, 2), blk, GSM_TOTAL>>>(
        ahi + (size_t)8952 * 512, alo + (size_t)8952 * 512,
        pos_buf, nullptr, nullptr, 191, D_, nullptr);

    // ---- BD precompute + fused attention ----
    bd_kernel<<<dim3(C_, 64), blk, SMEM_BD>>>(pbv);
    fused_attn_kernel<<<dim3(C_, 64), blk, FA_TOTAL>>>(lens, pbu);

    // ---- output projection ----
    conv_a_kernel<<<dim3((8704 * 128 + 255) / 256), blk>>>(
        attn_buf, attn_buf, attn_buf, attn_buf, 8704, 8704, 8704, 8704, 0);
    conv_w_kernel<<<dim3(1024), blk>>>(W_out, 512 * 512);
    gemm_tc_kernel<<<dim3(4, 68), blk, GSM_TOTAL>>>(
        ahi, alo, out, nullptr, nullptr, (R_ + U_) * B_, D_, b_out);
    clip_kernel<<<dim3(256), blk>>>(out);
}